// round 14
// baseline (speedup 1.0000x reference)
#include <cuda_runtime.h>
#include <cuda_bf16.h>

// out[n, j] = x[n, j] + (1/512) * sum_{k=512..1023} x[n, k]
// x: [131072, 1024] f32, out: [131072, 512] f32
//
// Converged configuration (best wall across 13 rounds: 114.75us), with the
// final untested cache-hint cell: __ldcg loads (L1 bypass — zero-reuse
// streaming reads) + __stcs store (evict-first write-once output).
// 256-thread block = 2 independent rows x 128 threads, one __syncthreads.
// MLP_p1=2 per thread.
//
// Kernel is pinned at the HBM read/write-turnaround ceiling (85-88% of
// 8TB/s in every measured config); traffic (768 MiB) is irreducible.
// Ruled out by measurement: persistent grids (+9us wall), named barriers
// (occupancy collapse), MLP=8 (L1tex queue contention), 4-row coupling,
// software pipelining.

static constexpr int ROW_IN  = 1024;
static constexpr int ROW_OUT = 512;
static constexpr int THREADS = 256;              // 2 rows x 128 threads

__global__ __launch_bounds__(THREADS)
void projection_kernel(const float* __restrict__ x,
                       float* __restrict__ out)
{
    int sub  = threadIdx.x >> 7;                  // row group 0/1
    int tid  = threadIdx.x & 127;                 // 0..127 within row
    int lane = threadIdx.x & 31;
    int warp = (threadIdx.x >> 5) & 3;            // warp within group

    size_t row = (size_t)blockIdx.x * 2 + sub;

    const float4* xrow = reinterpret_cast<const float4*>(x + row * ROW_IN);
    float4*       orow = reinterpret_cast<float4*>(out + row * ROW_OUT);

    // front-batch both loads (MLP_p1 = 2), L1-bypass policy
    float4 t = __ldcg(&xrow[128 + tid]);   // tail: feeds reduction
    float4 h = __ldcg(&xrow[tid]);         // head: held for the add

    float s = (t.x + t.y) + (t.z + t.w);

    #pragma unroll
    for (int off = 16; off > 0; off >>= 1)
        s += __shfl_xor_sync(0xFFFFFFFFu, s, off);

    __shared__ float partial[8];           // 4 warps x 2 rows
    if (lane == 0) partial[sub * 4 + warp] = s;
    __syncthreads();

    float total = (partial[sub * 4 + 0] + partial[sub * 4 + 1])
                + (partial[sub * 4 + 2] + partial[sub * 4 + 3]);
    float mean = total * (1.0f / 512.0f);

    h.x += mean; h.y += mean; h.z += mean; h.w += mean;

    __stcs(&orow[tid], h);
}

extern "C" void kernel_launch(void* const* d_in, const int* in_sizes, int n_in,
                              void* d_out, int out_size)
{
    const float* x = (const float*)d_in[0];
    float* out = (float*)d_out;

    int n_rows = in_sizes[0] / ROW_IN;     // 131072, even
    int blocks = n_rows / 2;               // 65536

    projection_kernel<<<blocks, THREADS>>>(x, out);
}